// round 12
// baseline (speedup 1.0000x reference)
#include <cuda_runtime.h>
#include <cuda_fp16.h>

#define SS 512
#define CC 64
#define VV 4
#define NFACES 400000
#define NP (SS*SS)             // 262144 pixels per view
#define VW ((NFACES+31)/32)    // 12500 words per view bitmask
#define NMAX 200000
#define NB 1024                // buckets: 16 x-tiles (32px) x 64 y-tiles (8px)
#define TPX 33                 // staged tile cols (32 + 1 corner overhang)
#define TPY 9                  // staged tile rows (8 + 1)
#define NPIX (TPX*TPY)         // 297 pixels
#define SP2 17                 // uint2 per pixel (16 data = 64 half + 1 pad)
#define VS2 (NPIX*SP2)         // 5049 uint2 per view
#define SMEM_DYN (VV*VS2*8)    // 161568 bytes

// Scratch (static device allocations; no runtime mallocs allowed)
__device__ unsigned g_vis[VV * VW];      // per-view face visibility bitmask
__device__ float    g_P[VV * 12];        // fused camera: rows of K@R (3x3) + K@t
__device__ int      g_key[NMAX];
__device__ int      g_perm[NMAX];
__device__ unsigned g_hist[NB];
__device__ unsigned g_bstart[NB];        // bucket start (stable copy)
__device__ unsigned g_off[NB];           // scatter cursor (consumed)

// ---------------------------------------------------------------------------
__global__ void clear_kernel() {
    int i = blockIdx.x * blockDim.x + threadIdx.x;
    if (i < VV * VW) g_vis[i] = 0u;
    if (i < NB) g_hist[i] = 0u;
}

__global__ void scatter_vis_kernel(const int* __restrict__ p2f) {
    int i = blockIdx.x * blockDim.x + threadIdx.x;
    if (i >= VV * NP) return;
    int f = __ldcs(&p2f[i]);
    if (f >= 0) {
        int v = i >> 18;
        atomicOr(&g_vis[v * VW + (f >> 5)], 1u << (f & 31));
    }
}

__global__ void cam_kernel(const float* __restrict__ Rm, const float* __restrict__ tm,
                           const float* __restrict__ Km) {
    int v = threadIdx.x;
    if (v >= VV) return;
    const float* R = Rm + v * 9;
    const float* t = tm + v * 3;
    const float* K = Km + v * 9;
    #pragma unroll
    for (int r = 0; r < 3; r++) {
        #pragma unroll
        for (int c = 0; c < 3; c++)
            g_P[v * 12 + r * 4 + c] = K[r*3+0]*R[0*3+c] + K[r*3+1]*R[1*3+c] + K[r*3+2]*R[2*3+c];
        g_P[v * 12 + r * 4 + 3] = K[r*3+0]*t[0] + K[r*3+1]*t[1] + K[r*3+2]*t[2];
    }
}

__device__ __forceinline__ void proj_xy(float px, float py, float pz, int v,
                                        float* x, float* y) {
    const float* P = g_P + v * 12;
    float u  = P[0]*px + P[1]*py + P[2] *pz + P[3];
    float w_ = P[4]*px + P[5]*py + P[6] *pz + P[7];
    float zz = P[8]*px + P[9]*py + P[10]*pz + P[11];
    float rz = __frcp_rn(zz);
    *x = u * rz; *y = w_ * rz;
}

// bucket keys from view-0 projection, smem-aggregated histogram
__global__ __launch_bounds__(256) void key_kernel(const float* __restrict__ verts, int n) {
    __shared__ unsigned h[NB];
    for (int w = threadIdx.x; w < NB; w += 256) h[w] = 0u;
    __syncthreads();
    for (int i = blockIdx.x * 256 + threadIdx.x; i < n; i += gridDim.x * 256) {
        float x, y;
        proj_xy(verts[3*i], verts[3*i+1], verts[3*i+2], 0, &x, &y);
        int xi = min(max((int)floorf(x), 0), SS-1);
        int yi = min(max((int)floorf(y), 0), SS-1);
        int key = (yi >> 3) * 16 + (xi >> 5);
        g_key[i] = key;
        atomicAdd(&h[key], 1u);
    }
    __syncthreads();
    for (int w = threadIdx.x; w < NB; w += 256) {
        unsigned c = h[w];
        if (c) atomicAdd(&g_hist[w], c);
    }
}

__global__ __launch_bounds__(1024) void prefix_kernel() {
    __shared__ unsigned s[NB];
    int t = threadIdx.x;
    unsigned v = g_hist[t];
    s[t] = v; __syncthreads();
    for (int d = 1; d < NB; d <<= 1) {
        unsigned x = (t >= d) ? s[t - d] : 0u;
        __syncthreads(); s[t] += x; __syncthreads();
    }
    unsigned excl = s[t] - v;
    g_bstart[t] = excl;
    g_off[t] = excl;
}

__global__ __launch_bounds__(256) void scatter_perm_kernel(int n) {
    int i = blockIdx.x * blockDim.x + threadIdx.x;
    if (i >= n) return;
    unsigned pos = atomicAdd(&g_off[g_key[i]], 1u);
    g_perm[pos] = i;
}

// accumulate 8 fp16 channels (one uint4) with weight w into acc[8]
__device__ __forceinline__ void accum8(float* acc, uint4 q, float w) {
    __half2 h0 = *(__half2*)&q.x, h1 = *(__half2*)&q.y;
    __half2 h2 = *(__half2*)&q.z, h3 = *(__half2*)&q.w;
    float2 f0 = __half22float2(h0), f1 = __half22float2(h1);
    float2 f2 = __half22float2(h2), f3 = __half22float2(h3);
    acc[0] = fmaf(w, f0.x, acc[0]); acc[1] = fmaf(w, f0.y, acc[1]);
    acc[2] = fmaf(w, f1.x, acc[2]); acc[3] = fmaf(w, f1.y, acc[3]);
    acc[4] = fmaf(w, f2.x, acc[4]); acc[5] = fmaf(w, f2.y, acc[5]);
    acc[6] = fmaf(w, f3.x, acc[6]); acc[7] = fmaf(w, f3.y, acc[7]);
}

// fallback: direct gmem bilinear for one (vertex, view) corner set (generality guard)
__device__ __forceinline__ void accum_fb(float* acc, const float* __restrict__ feat,
                                         int v, int ck, int gp, float w) {
    if (w == 0.0f) return;
    #pragma unroll
    for (int k = 0; k < 8; k++)
        acc[k] = fmaf(w, __ldg(&feat[((size_t)(v*CC + ck*8 + k))*NP + gp]), acc[k]);
}

// ---------------------------------------------------------------------------
// Fused stage+gather: one block per bucket. Stage 33x9 px x 64ch x 4 views
// (fp16, channel-last) into smem, then interpolate the bucket's vertices.
__global__ __launch_bounds__(512) void fused_kernel(
    float* __restrict__ out,
    const float* __restrict__ verts, const int* __restrict__ faces,
    const float* __restrict__ feat, int n)
{
    extern __shared__ uint2 s_tile[];          // [VV][NPIX][SP2]
    __shared__ int           s_ip[64];
    __shared__ int4          s_off[64][VV];
    __shared__ float4        s_w[64][VV];
    __shared__ unsigned char s_fb[64][VV];

    int b = blockIdx.x;
    int cnt = (int)g_hist[b];
    if (cnt == 0) return;
    int start = (int)g_bstart[b];
    int xt = (b & 15) << 5;     // tile origin x (32-wide)
    int yt = (b >> 4) << 3;     // tile origin y (8-tall)

    int t = threadIdx.x, lane = t & 31, wid = t >> 5;  // 16 warps

    // --- stage main 32 columns: items (v, cpair, y) = 4*32*9 = 1152, 8/warp-batch for MLP
    const int NIT = VV * 32 * TPY; // 1152
    for (int base = wid; base < NIT; base += 16 * 8) {
        float f[16]; int wrd[8];
        #pragma unroll
        for (int u = 0; u < 8; u++) {
            int it = base + u * 16;
            int v  = it / (32 * TPY);
            int rem = it - v * (32 * TPY);
            int cp = rem / TPY;
            int y  = rem - cp * TPY;
            int yy = min(yt + y, SS - 1);
            const float* g = feat + ((size_t)(v*CC + 2*cp))*NP + yy*SS + xt + lane;
            f[2*u]   = __ldcs(g);
            f[2*u+1] = __ldcs(g + NP);
            wrd[u] = (v * VS2 + (y * TPX + lane) * SP2) * 2 + cp;
        }
        #pragma unroll
        for (int u = 0; u < 8; u++) {
            __half2 h = __floats2half2_rn(f[2*u], f[2*u+1]);
            ((unsigned*)s_tile)[wrd[u]] = *(unsigned*)&h;
        }
    }
    // --- stage residual column px=32
    for (int it = t; it < NIT; it += 512) {
        int v  = it / (32 * TPY);
        int rem = it - v * (32 * TPY);
        int cp = rem / TPY;
        int y  = rem - cp * TPY;
        int yy = min(yt + y, SS - 1);
        int xx = min(xt + 32, SS - 1);
        const float* g = feat + ((size_t)(v*CC + 2*cp))*NP + yy*SS + xx;
        __half2 h = __floats2half2_rn(__ldcs(g), __ldcs(g + NP));
        ((unsigned*)s_tile)[(v * VS2 + (y * TPX + 32) * SP2) * 2 + cp] = *(unsigned*)&h;
    }
    __syncthreads();

    // --- process bucket vertices in chunks of 64
    for (int s = 0; s < cnt; s += 64) {
        int m = min(64, cnt - s);

        if (t < 256) {
            int j = t >> 2, v = t & 3;
            if (j < m) {
                int ip = g_perm[start + s + j];
                if (v == 0) s_ip[j] = ip;
                float px = verts[3*ip], py = verts[3*ip+1], pz = verts[3*ip+2];
                int f = faces[ip];
                int msum = 0, mv = 0;
                #pragma unroll
                for (int vv = 0; vv < VV; vv++) {
                    int bb = (g_vis[vv * VW + (f >> 5)] >> (f & 31)) & 1;
                    msum += bb;
                    if (vv == v) mv = bb;
                }
                float inv = 1.0f / (float)(msum ? msum : VV);
                float bw  = (msum ? (float)mv : 1.0f) * inv;

                float x, y;
                proj_xy(px, py, pz, v, &x, &y);
                float x0f = floorf(x), y0f = floorf(y);
                float x1f = x0f + 1.0f, y1f = y0f + 1.0f;
                float wx1 = x - x0f, wx0 = 1.0f - wx1;
                float wy1 = y - y0f, wy0 = 1.0f - wy1;

                bool vx0 = (x0f >= 0.0f) && (x0f <= (float)(SS-1));
                bool vx1 = (x1f >= 0.0f) && (x1f <= (float)(SS-1));
                bool vy0 = (y0f >= 0.0f) && (y0f <= (float)(SS-1));
                bool vy1 = (y1f >= 0.0f) && (y1f <= (float)(SS-1));

                int xc0 = min(max((int)x0f, 0), SS-1);
                int xc1 = min(max((int)x0f + 1, 0), SS-1);
                int yc0 = min(max((int)y0f, 0), SS-1);
                int yc1 = min(max((int)y0f + 1, 0), SS-1);

                int px0 = xc0 - xt, px1 = xc1 - xt;
                int py0 = yc0 - yt, py1 = yc1 - yt;
                bool ok = (px0 >= 0) && (px1 <= 32) && (py0 >= 0) && (py1 <= 8);
                if (ok) {
                    s_off[j][v] = make_int4(py0*TPX+px0, py0*TPX+px1,
                                            py1*TPX+px0, py1*TPX+px1);
                    s_fb[j][v] = 0;
                } else {
                    s_off[j][v] = make_int4(yc0*SS+xc0, yc0*SS+xc1,
                                            yc1*SS+xc0, yc1*SS+xc1);
                    s_fb[j][v] = 1;
                }
                float4 wq;
                wq.x = bw * wx0 * wy0 * (float)(vx0 && vy0);
                wq.y = bw * wx1 * wy0 * (float)(vx1 && vy0);
                wq.z = bw * wx0 * wy1 * (float)(vx0 && vy1);
                wq.w = bw * wx1 * wy1 * (float)(vx1 && vy1);
                s_w[j][v] = wq;
            }
        }
        __syncthreads();

        int j = t >> 3, ck = t & 7;
        if (j < m) {
            int ip = s_ip[j];
            float acc[8] = {0.f,0.f,0.f,0.f,0.f,0.f,0.f,0.f};
            #pragma unroll
            for (int v = 0; v < VV; v++) {
                float4 w = s_w[j][v];
                if (w.x + w.y + w.z + w.w != 0.0f) {
                    int4 o = s_off[j][v];
                    if (!s_fb[j][v]) {
                        int bu = v * VS2 + ck * 2;
                        uint2 a0 = s_tile[bu + o.x*SP2], a1 = s_tile[bu + o.x*SP2 + 1];
                        uint2 b0 = s_tile[bu + o.y*SP2], b1 = s_tile[bu + o.y*SP2 + 1];
                        uint2 c0 = s_tile[bu + o.z*SP2], c1 = s_tile[bu + o.z*SP2 + 1];
                        uint2 d0 = s_tile[bu + o.w*SP2], d1 = s_tile[bu + o.w*SP2 + 1];
                        accum8(acc, make_uint4(a0.x,a0.y,a1.x,a1.y), w.x);
                        accum8(acc, make_uint4(b0.x,b0.y,b1.x,b1.y), w.y);
                        accum8(acc, make_uint4(c0.x,c0.y,c1.x,c1.y), w.z);
                        accum8(acc, make_uint4(d0.x,d0.y,d1.x,d1.y), w.w);
                    } else {
                        accum_fb(acc, feat, v, ck, o.x, w.x);
                        accum_fb(acc, feat, v, ck, o.y, w.y);
                        accum_fb(acc, feat, v, ck, o.z, w.z);
                        accum_fb(acc, feat, v, ck, o.w, w.w);
                    }
                }
            }
            float4* O = (float4*)(out + (size_t)ip * CC + ck * 8);
            __stcs(O,     make_float4(acc[0], acc[1], acc[2], acc[3]));
            __stcs(O + 1, make_float4(acc[4], acc[5], acc[6], acc[7]));
        }
        __syncthreads();
    }
}

// ---------------------------------------------------------------------------
// One-time host setup (first call is the uncaptured correctness run)
static cudaStream_t g_s1 = nullptr;
static cudaEvent_t  g_eC = nullptr, g_eV = nullptr;

extern "C" void kernel_launch(void* const* d_in, const int* in_sizes, int n_in,
                              void* d_out, int out_size) {
    const float* verts = nullptr;
    const int*   faces = nullptr;
    const float* Rm = nullptr, *tm = nullptr, *Km = nullptr, *feat = nullptr;
    const int*   p2f = nullptr;
    int n36 = 0;
    for (int i = 0; i < n_in; i++) {
        int s = in_sizes[i];
        if      (s == 600000)   verts = (const float*)d_in[i];
        else if (s == 200000)   faces = (const int*)d_in[i];
        else if (s == 36)       { if (n36++ == 0) Rm = (const float*)d_in[i]; else Km = (const float*)d_in[i]; }
        else if (s == 12)       tm = (const float*)d_in[i];
        else if (s == 67108864) feat = (const float*)d_in[i];
        else if (s == 1048576)  p2f = (const int*)d_in[i];
    }
    int n = 200000;

    if (g_s1 == nullptr) {
        cudaStreamCreateWithFlags(&g_s1, cudaStreamNonBlocking);
        cudaEventCreateWithFlags(&g_eC, cudaEventDisableTiming);
        cudaEventCreateWithFlags(&g_eV, cudaEventDisableTiming);
        cudaFuncSetAttribute(fused_kernel, cudaFuncAttributeMaxDynamicSharedMemorySize, SMEM_DYN);
    }

    // main: clear -> cam -> key -> prefix -> scatter_perm -> fused
    clear_kernel<<<(VV * VW + 255) / 256, 256>>>();
    cudaEventRecord(g_eC, 0);
    cam_kernel<<<1, 32>>>(Rm, tm, Km);
    key_kernel<<<148, 256>>>(verts, n);
    prefix_kernel<<<1, NB>>>();
    scatter_perm_kernel<<<(n + 255) / 256, 256>>>(n);

    // side: vis scatter (overlaps the key/sort chain)
    cudaStreamWaitEvent(g_s1, g_eC, 0);
    scatter_vis_kernel<<<(VV * NP + 255) / 256, 256, 0, g_s1>>>(p2f);
    cudaEventRecord(g_eV, g_s1);
    cudaStreamWaitEvent(0, g_eV, 0);

    fused_kernel<<<NB, 512, SMEM_DYN>>>((float*)d_out, verts, faces, feat, n);
}

// round 13
// speedup vs baseline: 1.8172x; 1.8172x over previous
#include <cuda_runtime.h>
#include <cuda_fp16.h>

#define SS 512
#define CC 64
#define VV 4
#define NFACES 400000
#define NP (SS*SS)             // 262144 pixels per view
#define VW ((NFACES+31)/32)    // 12500 words per view bitmask
#define NMAX 200000
#define TPW 128                // transpose tile width (pixels)

// Scratch (static device allocations; no runtime mallocs allowed)
__device__ __align__(128) __half g_featT[(size_t)VV * NP * CC]; // 128 MiB, channel-last fp16
__device__ unsigned g_vis[VV * VW];      // per-view face visibility bitmask
__device__ float    g_P[VV * 12];        // fused camera: rows of K@R (3x3) + K@t, [r*4+c]

// ---------------------------------------------------------------------------
// 1. clear visibility bitmask
__global__ void clear_vis_kernel() {
    int i = blockIdx.x * blockDim.x + threadIdx.x;
    if (i < VV * VW) g_vis[i] = 0u;
}

// 2. scatter pix_to_face into visibility bitmask
__global__ void scatter_vis_kernel(const int* __restrict__ p2f) {
    int i = blockIdx.x * blockDim.x + threadIdx.x;
    if (i >= VV * NP) return;
    int f = __ldcs(&p2f[i]);
    if (f >= 0) {
        int v = i >> 18; // i / NP
        atomicOr(&g_vis[v * VW + (f >> 5)], 1u << (f & 31));
    }
}

// 3. fuse cameras: P = K@R, q = K@t
__global__ void cam_kernel(const float* __restrict__ Rm, const float* __restrict__ tm,
                           const float* __restrict__ Km) {
    int v = threadIdx.x;
    if (v >= VV) return;
    const float* R = Rm + v * 9;
    const float* t = tm + v * 3;
    const float* K = Km + v * 9;
    #pragma unroll
    for (int r = 0; r < 3; r++) {
        #pragma unroll
        for (int c = 0; c < 3; c++)
            g_P[v * 12 + r * 4 + c] = K[r*3+0]*R[0*3+c] + K[r*3+1]*R[1*3+c] + K[r*3+2]*R[2*3+c];
        g_P[v * 12 + r * 4 + 3] = K[r*3+0]*t[0] + K[r*3+1]*t[1] + K[r*3+2]*t[2];
    }
}

// 4. transpose feature [V,C,S,S] fp32 -> [V,S,S,C] fp16.
//    WIDE tile: 64 channels x 128 pixels. Each warp reads 512B contiguous per
//    channel row (4x128B bursts); writes stay 128B-contiguous per pixel row.
__global__ __launch_bounds__(256) void transpose_feat_kernel(const float* __restrict__ feat) {
    __shared__ float tile[CC][TPW + 1];
    int v  = blockIdx.y;
    int p0 = blockIdx.x * TPW;
    const float* in = feat + (size_t)v * CC * NP + p0;
    int tx = threadIdx.x & 31, tw = threadIdx.x >> 5; // lane, warp 0..7
    // read: warp tw handles channel rows tw*8..tw*8+7, 4 x 128B segments each
    #pragma unroll
    for (int j = 0; j < 8; j++) {
        int r = tw * 8 + j;
        const float* row = in + (size_t)r * NP;
        #pragma unroll
        for (int s = 0; s < 4; s++)
            tile[r][tx + s * 32] = __ldcs(&row[tx + s * 32]);
    }
    __syncthreads();
    // write: warp tw handles pixels tw*16..tw*16+15; lane = channel-pair
    __half2* out = ((__half2*)g_featT) + ((size_t)v * NP + p0) * 32;
    #pragma unroll
    for (int k = 0; k < 16; k++) {
        int p = tw * 16 + k;
        __half2 h = __floats2half2_rn(tile[2*tx][p], tile[2*tx+1][p]);
        out[(size_t)p * 32 + tx] = h;   // warp writes 32 consecutive half2 = 128B
    }
}

// shared projection: raw pixel-space xy for (vertex, view)
__device__ __forceinline__ void proj_xy(float px, float py, float pz, int v,
                                        float* x, float* y) {
    const float* P = g_P + v * 12;
    float u  = P[0]*px + P[1]*py + P[2] *pz + P[3];
    float w_ = P[4]*px + P[5]*py + P[6] *pz + P[7];
    float zz = P[8]*px + P[9]*py + P[10]*pz + P[11];
    float rz = __frcp_rn(zz);
    *x = u * rz; *y = w_ * rz;
}

// accumulate 8 fp16 channels (one uint4) with weight w into acc[8]
__device__ __forceinline__ void accum8(float* acc, uint4 q, float w) {
    __half2 h0 = *(__half2*)&q.x, h1 = *(__half2*)&q.y;
    __half2 h2 = *(__half2*)&q.z, h3 = *(__half2*)&q.w;
    float2 f0 = __half22float2(h0), f1 = __half22float2(h1);
    float2 f2 = __half22float2(h2), f3 = __half22float2(h3);
    acc[0] = fmaf(w, f0.x, acc[0]); acc[1] = fmaf(w, f0.y, acc[1]);
    acc[2] = fmaf(w, f1.x, acc[2]); acc[3] = fmaf(w, f1.y, acc[3]);
    acc[4] = fmaf(w, f2.x, acc[4]); acc[5] = fmaf(w, f2.y, acc[5]);
    acc[6] = fmaf(w, f3.x, acc[6]); acc[7] = fmaf(w, f3.y, acc[7]);
}

// 5. fused meta + gather: 32 vertices per 256-thread block (proven R7 version).
__global__ __launch_bounds__(256) void gather_kernel(
    float* __restrict__ out,
    const float* __restrict__ verts, const int* __restrict__ faces, int n)
{
    __shared__ int4   s_off[32][VV];
    __shared__ float4 s_w[32][VV];

    int vb = blockIdx.x * 32;
    int t  = threadIdx.x;

    if (t < 128) {
        int j = t >> 2, v = t & 3;
        int i = vb + j;
        if (i < n) {
            float px = verts[3*i], py = verts[3*i+1], pz = verts[3*i+2];
            int f = faces[i];
            int msum = 0, mv = 0;
            #pragma unroll
            for (int vv = 0; vv < VV; vv++) {
                int b = (g_vis[vv * VW + (f >> 5)] >> (f & 31)) & 1;
                msum += b;
                if (vv == v) mv = b;
            }
            float inv = 1.0f / (float)(msum ? msum : VV);
            float bw  = (msum ? (float)mv : 1.0f) * inv;

            float x, y;
            proj_xy(px, py, pz, v, &x, &y);
            float x0f = floorf(x), y0f = floorf(y);
            float x1f = x0f + 1.0f, y1f = y0f + 1.0f;
            float wx1 = x - x0f, wx0 = 1.0f - wx1;
            float wy1 = y - y0f, wy0 = 1.0f - wy1;

            bool vx0 = (x0f >= 0.0f) && (x0f <= (float)(SS-1));
            bool vx1 = (x1f >= 0.0f) && (x1f <= (float)(SS-1));
            bool vy0 = (y0f >= 0.0f) && (y0f <= (float)(SS-1));
            bool vy1 = (y1f >= 0.0f) && (y1f <= (float)(SS-1));

            int xc0 = (int)fminf(fmaxf(x0f, 0.0f), (float)(SS-1));
            int xc1 = (int)fminf(fmaxf(x1f, 0.0f), (float)(SS-1));
            int yc0 = (int)fminf(fmaxf(y0f, 0.0f), (float)(SS-1));
            int yc1 = (int)fminf(fmaxf(y1f, 0.0f), (float)(SS-1));

            int baseV = v * NP;
            s_off[j][v] = make_int4((baseV + yc0 * SS + xc0) * 8,
                                    (baseV + yc0 * SS + xc1) * 8,
                                    (baseV + yc1 * SS + xc0) * 8,
                                    (baseV + yc1 * SS + xc1) * 8);
            float4 wq;
            wq.x = bw * wx0 * wy0 * (float)(vx0 && vy0);
            wq.y = bw * wx1 * wy0 * (float)(vx1 && vy0);
            wq.z = bw * wx0 * wy1 * (float)(vx0 && vy1);
            wq.w = bw * wx1 * wy1 * (float)(vx1 && vy1);
            s_w[j][v] = wq;
        }
    }
    __syncthreads();

    int j = t >> 3;
    int i = vb + j;
    int ck = t & 7;           // channel chunk (8 channels)
    if (i >= n) return;

    const uint4* B = (const uint4*)g_featT;
    float acc[8] = {0.f,0.f,0.f,0.f,0.f,0.f,0.f,0.f};
    #pragma unroll
    for (int v = 0; v < VV; v++) {
        float4 w = s_w[j][v];
        if (w.x + w.y + w.z + w.w != 0.0f) {
            int4 o = s_off[j][v];
            uint4 fa = B[o.x + ck];
            uint4 fb = B[o.y + ck];
            uint4 fc = B[o.z + ck];
            uint4 fd = B[o.w + ck];
            accum8(acc, fa, w.x);
            accum8(acc, fb, w.y);
            accum8(acc, fc, w.z);
            accum8(acc, fd, w.w);
        }
    }
    float4* O = (float4*)(out + (size_t)i * CC + ck * 8);
    __stcs(O,     make_float4(acc[0], acc[1], acc[2], acc[3]));
    __stcs(O + 1, make_float4(acc[4], acc[5], acc[6], acc[7]));
}

// ---------------------------------------------------------------------------
// Side stream + fork/join events: created once (first call is the uncaptured
// correctness run); reused on every call so captured work is identical.
static cudaStream_t g_side = nullptr;
static cudaEvent_t  g_evFork = nullptr, g_evJoin = nullptr;

extern "C" void kernel_launch(void* const* d_in, const int* in_sizes, int n_in,
                              void* d_out, int out_size) {
    const float* verts = nullptr;
    const int*   faces = nullptr;
    const float* Rm = nullptr, *tm = nullptr, *Km = nullptr, *feat = nullptr;
    const int*   p2f = nullptr;
    int n36 = 0;
    for (int i = 0; i < n_in; i++) {
        int s = in_sizes[i];
        if      (s == 600000)   verts = (const float*)d_in[i];
        else if (s == 200000)   faces = (const int*)d_in[i];
        else if (s == 36)       { if (n36++ == 0) Rm = (const float*)d_in[i]; else Km = (const float*)d_in[i]; }
        else if (s == 12)       tm = (const float*)d_in[i];
        else if (s == 67108864) feat = (const float*)d_in[i];
        else if (s == 1048576)  p2f = (const int*)d_in[i];
    }
    int n = 200000;

    if (g_side == nullptr) {
        cudaStreamCreateWithFlags(&g_side, cudaStreamNonBlocking);
        cudaEventCreateWithFlags(&g_evFork, cudaEventDisableTiming);
        cudaEventCreateWithFlags(&g_evJoin, cudaEventDisableTiming);
    }

    // fork: side branch handles visibility + camera (independent of feature)
    cudaEventRecord(g_evFork, 0);
    cudaStreamWaitEvent(g_side, g_evFork, 0);
    clear_vis_kernel<<<(VV * VW + 255) / 256, 256, 0, g_side>>>();
    scatter_vis_kernel<<<(VV * NP + 255) / 256, 256, 0, g_side>>>(p2f);
    cam_kernel<<<1, 32, 0, g_side>>>(Rm, tm, Km);
    cudaEventRecord(g_evJoin, g_side);

    // main branch: full feature transpose (the long pole), wide tiles
    transpose_feat_kernel<<<dim3(NP / TPW, VV), 256>>>(feat);

    // join: gather needs featT + vis + P
    cudaStreamWaitEvent(0, g_evJoin, 0);
    gather_kernel<<<(n + 31) / 32, 256>>>((float*)d_out, verts, faces, n);
}

// round 14
// speedup vs baseline: 1.9280x; 1.0610x over previous
#include <cuda_runtime.h>
#include <cuda_fp16.h>

#define SS 512
#define CC 64
#define VV 4
#define NFACES 400000
#define NP (SS*SS)             // 262144 pixels per view
#define VW ((NFACES+31)/32)    // 12500 words per view bitmask
#define NMAX 200000

// Scratch (static device allocations; no runtime mallocs allowed)
__device__ __align__(128) __half g_featT[(size_t)VV * NP * CC]; // 128 MiB, channel-last fp16
__device__ unsigned g_vis[VV * VW];      // per-view face visibility bitmask
__device__ float    g_P[VV * 12];        // fused camera: rows of K@R (3x3) + K@t, [r*4+c]

// ---------------------------------------------------------------------------
// 1. clear visibility bitmask
__global__ void clear_vis_kernel() {
    int i = blockIdx.x * blockDim.x + threadIdx.x;
    if (i < VV * VW) g_vis[i] = 0u;
}

// 2. scatter pix_to_face into visibility bitmask
__global__ void scatter_vis_kernel(const int* __restrict__ p2f) {
    int i = blockIdx.x * blockDim.x + threadIdx.x;
    if (i >= VV * NP) return;
    int f = __ldcs(&p2f[i]);
    if (f >= 0) {
        int v = i >> 18; // i / NP
        atomicOr(&g_vis[v * VW + (f >> 5)], 1u << (f & 31));
    }
}

// 3. fuse cameras: P = K@R, q = K@t
__global__ void cam_kernel(const float* __restrict__ Rm, const float* __restrict__ tm,
                           const float* __restrict__ Km) {
    int v = threadIdx.x;
    if (v >= VV) return;
    const float* R = Rm + v * 9;
    const float* t = tm + v * 3;
    const float* K = Km + v * 9;
    #pragma unroll
    for (int r = 0; r < 3; r++) {
        #pragma unroll
        for (int c = 0; c < 3; c++)
            g_P[v * 12 + r * 4 + c] = K[r*3+0]*R[0*3+c] + K[r*3+1]*R[1*3+c] + K[r*3+2]*R[2*3+c];
        g_P[v * 12 + r * 4 + 3] = K[r*3+0]*t[0] + K[r*3+1]*t[1] + K[r*3+2]*t[2];
    }
}

// 4. transpose feature [V,C,S,S] fp32 -> [V,S,S,C] fp16 (EXACT proven R7 version:
//    32-px tiles, 8KB smem, high occupancy — measured 66.3us @ 70.4% DRAM = LTS cap)
__global__ __launch_bounds__(256) void transpose_feat_kernel(const float* __restrict__ feat) {
    __shared__ float tile[CC][33];
    int v  = blockIdx.y;
    int p0 = blockIdx.x * 32;
    const float* in = feat + (size_t)v * CC * NP + p0;
    int tx = threadIdx.x & 31, tw = threadIdx.x >> 5;
    #pragma unroll
    for (int j = 0; j < 8; j++) {
        int r = tw * 8 + j;
        tile[r][tx] = __ldcs(&in[(size_t)r * NP + tx]);
    }
    __syncthreads();
    __half2* out = ((__half2*)g_featT) + ((size_t)v * NP + p0) * 32;
    int cp = tx;
    int pb = tw;
    #pragma unroll
    for (int k = 0; k < 4; k++) {
        int p = pb + k * 8;
        __half2 h = __floats2half2_rn(tile[2*cp][p], tile[2*cp+1][p]);
        out[(size_t)p * 32 + cp] = h;
    }
}

// shared projection: raw pixel-space xy for (vertex, view)
__device__ __forceinline__ void proj_xy(float px, float py, float pz, int v,
                                        float* x, float* y) {
    const float* P = g_P + v * 12;
    float u  = P[0]*px + P[1]*py + P[2] *pz + P[3];
    float w_ = P[4]*px + P[5]*py + P[6] *pz + P[7];
    float zz = P[8]*px + P[9]*py + P[10]*pz + P[11];
    float rz = __frcp_rn(zz);
    *x = u * rz; *y = w_ * rz;
}

// accumulate 8 fp16 channels (one uint4) with weight w into acc[8]
__device__ __forceinline__ void accum8(float* acc, uint4 q, float w) {
    __half2 h0 = *(__half2*)&q.x, h1 = *(__half2*)&q.y;
    __half2 h2 = *(__half2*)&q.z, h3 = *(__half2*)&q.w;
    float2 f0 = __half22float2(h0), f1 = __half22float2(h1);
    float2 f2 = __half22float2(h2), f3 = __half22float2(h3);
    acc[0] = fmaf(w, f0.x, acc[0]); acc[1] = fmaf(w, f0.y, acc[1]);
    acc[2] = fmaf(w, f1.x, acc[2]); acc[3] = fmaf(w, f1.y, acc[3]);
    acc[4] = fmaf(w, f2.x, acc[4]); acc[5] = fmaf(w, f2.y, acc[5]);
    acc[6] = fmaf(w, f3.x, acc[6]); acc[7] = fmaf(w, f3.y, acc[7]);
}

// 5. fused meta + gather: 32 vertices per 256-thread block.
//    Phase 2 is BRANCH-FREE: masked views read featT line 0 (warp-uniform
//    broadcast, L1-hot) with weight 0. Loads issue in 2 batches of 8
//    independent uint4s -> MLP 8, accum overlaps the next batch.
__global__ __launch_bounds__(256) void gather_kernel(
    float* __restrict__ out,
    const float* __restrict__ verts, const int* __restrict__ faces, int n)
{
    __shared__ int4   s_off[32][VV];
    __shared__ float4 s_w[32][VV];

    int vb = blockIdx.x * 32;
    int t  = threadIdx.x;

    if (t < 128) {
        int j = t >> 2, v = t & 3;
        int i = vb + j;
        if (i < n) {
            float px = verts[3*i], py = verts[3*i+1], pz = verts[3*i+2];
            int f = faces[i];
            int msum = 0, mv = 0;
            #pragma unroll
            for (int vv = 0; vv < VV; vv++) {
                int b = (g_vis[vv * VW + (f >> 5)] >> (f & 31)) & 1;
                msum += b;
                if (vv == v) mv = b;
            }
            float inv = 1.0f / (float)(msum ? msum : VV);
            float bw  = (msum ? (float)mv : 1.0f) * inv;

            float x, y;
            proj_xy(px, py, pz, v, &x, &y);
            float x0f = floorf(x), y0f = floorf(y);
            float x1f = x0f + 1.0f, y1f = y0f + 1.0f;
            float wx1 = x - x0f, wx0 = 1.0f - wx1;
            float wy1 = y - y0f, wy0 = 1.0f - wy1;

            bool vx0 = (x0f >= 0.0f) && (x0f <= (float)(SS-1));
            bool vx1 = (x1f >= 0.0f) && (x1f <= (float)(SS-1));
            bool vy0 = (y0f >= 0.0f) && (y0f <= (float)(SS-1));
            bool vy1 = (y1f >= 0.0f) && (y1f <= (float)(SS-1));

            int xc0 = (int)fminf(fmaxf(x0f, 0.0f), (float)(SS-1));
            int xc1 = (int)fminf(fmaxf(x1f, 0.0f), (float)(SS-1));
            int yc0 = (int)fminf(fmaxf(y0f, 0.0f), (float)(SS-1));
            int yc1 = (int)fminf(fmaxf(y1f, 0.0f), (float)(SS-1));

            float4 wq;
            wq.x = bw * wx0 * wy0 * (float)(vx0 && vy0);
            wq.y = bw * wx1 * wy0 * (float)(vx1 && vy0);
            wq.z = bw * wx0 * wy1 * (float)(vx0 && vy1);
            wq.w = bw * wx1 * wy1 * (float)(vx1 && vy1);

            // predicate offsets here: dead views point at line 0 (broadcast)
            bool live = (wq.x + wq.y + wq.z + wq.w) != 0.0f;
            int baseV = v * NP;
            s_off[j][v] = live ? make_int4((baseV + yc0 * SS + xc0) * 8,
                                           (baseV + yc0 * SS + xc1) * 8,
                                           (baseV + yc1 * SS + xc0) * 8,
                                           (baseV + yc1 * SS + xc1) * 8)
                               : make_int4(0, 0, 0, 0);
            s_w[j][v] = wq;
        }
    }
    __syncthreads();

    int j = t >> 3;
    int i = vb + j;
    int ck = t & 7;           // channel chunk (8 channels)
    if (i >= n) return;

    const uint4* B = (const uint4*)g_featT;
    float acc[8] = {0.f,0.f,0.f,0.f,0.f,0.f,0.f,0.f};
    #pragma unroll
    for (int vp = 0; vp < 2; vp++) {
        // batch: 8 independent loads (2 views x 4 corners), no branches
        uint4 r[8];
        int4   o0 = s_off[j][vp*2],   o1 = s_off[j][vp*2+1];
        float4 w0 = s_w[j][vp*2],     w1 = s_w[j][vp*2+1];
        r[0] = B[o0.x + ck]; r[1] = B[o0.y + ck];
        r[2] = B[o0.z + ck]; r[3] = B[o0.w + ck];
        r[4] = B[o1.x + ck]; r[5] = B[o1.y + ck];
        r[6] = B[o1.z + ck]; r[7] = B[o1.w + ck];
        accum8(acc, r[0], w0.x); accum8(acc, r[1], w0.y);
        accum8(acc, r[2], w0.z); accum8(acc, r[3], w0.w);
        accum8(acc, r[4], w1.x); accum8(acc, r[5], w1.y);
        accum8(acc, r[6], w1.z); accum8(acc, r[7], w1.w);
    }
    float4* O = (float4*)(out + (size_t)i * CC + ck * 8);
    __stcs(O,     make_float4(acc[0], acc[1], acc[2], acc[3]));
    __stcs(O + 1, make_float4(acc[4], acc[5], acc[6], acc[7]));
}

// ---------------------------------------------------------------------------
// Side stream + fork/join events: created once (first call is the uncaptured
// correctness run); reused on every call so captured work is identical.
static cudaStream_t g_side = nullptr;
static cudaEvent_t  g_evFork = nullptr, g_evJoin = nullptr;

extern "C" void kernel_launch(void* const* d_in, const int* in_sizes, int n_in,
                              void* d_out, int out_size) {
    const float* verts = nullptr;
    const int*   faces = nullptr;
    const float* Rm = nullptr, *tm = nullptr, *Km = nullptr, *feat = nullptr;
    const int*   p2f = nullptr;
    int n36 = 0;
    for (int i = 0; i < n_in; i++) {
        int s = in_sizes[i];
        if      (s == 600000)   verts = (const float*)d_in[i];
        else if (s == 200000)   faces = (const int*)d_in[i];
        else if (s == 36)       { if (n36++ == 0) Rm = (const float*)d_in[i]; else Km = (const float*)d_in[i]; }
        else if (s == 12)       tm = (const float*)d_in[i];
        else if (s == 67108864) feat = (const float*)d_in[i];
        else if (s == 1048576)  p2f = (const int*)d_in[i];
    }
    int n = 200000;

    if (g_side == nullptr) {
        cudaStreamCreateWithFlags(&g_side, cudaStreamNonBlocking);
        cudaEventCreateWithFlags(&g_evFork, cudaEventDisableTiming);
        cudaEventCreateWithFlags(&g_evJoin, cudaEventDisableTiming);
    }

    // fork: side branch handles visibility + camera (independent of feature)
    cudaEventRecord(g_evFork, 0);
    cudaStreamWaitEvent(g_side, g_evFork, 0);
    clear_vis_kernel<<<(VV * VW + 255) / 256, 256, 0, g_side>>>();
    scatter_vis_kernel<<<(VV * NP + 255) / 256, 256, 0, g_side>>>(p2f);
    cam_kernel<<<1, 32, 0, g_side>>>(Rm, tm, Km);
    cudaEventRecord(g_evJoin, g_side);

    // main branch: full feature transpose (the long pole)
    transpose_feat_kernel<<<dim3(NP / 32, VV), 256>>>(feat);

    // join: gather needs featT + vis + P
    cudaStreamWaitEvent(0, g_evJoin, 0);
    gather_kernel<<<(n + 31) / 32, 256>>>((float*)d_out, verts, faces, n);
}